// round 4
// baseline (speedup 1.0000x reference)
#include <cuda_runtime.h>

// Closed form of the whole circuit:
//   e_w = cos(theta_w) * prod_{k<=w} cos(x_k)  -  sin(theta_w) * sin(x_w) * sin(x_{w+1})
// with sin(x_4) := 1.
// 4 elements per thread, loads hoisted for MLP=4 (the kernel is memory-latency
// bound otherwise: flat ~35% DRAM/L2/L1 with 17% issue in round 3).

#define ELTS 4

__global__ void __launch_bounds__(256)
qlayer_kernel(const float* __restrict__ x, const float* __restrict__ w,
              float* __restrict__ out, int n) {
    int t = blockIdx.x * blockDim.x + threadIdx.x;
    int b0 = t * ELTS;

    // weights: uniform across threads; one sincos set per thread, amortized.
    float4 wv = *reinterpret_cast<const float4*>(w);
    float sw0, cw0, sw1, cw1, sw2, cw2, sw3, cw3;
    __sincosf(wv.x, &sw0, &cw0);
    __sincosf(wv.y, &sw1, &cw1);
    __sincosf(wv.z, &sw2, &cw2);
    __sincosf(wv.w, &sw3, &cw3);

    if (b0 + (ELTS - 1) < n) {
        // Fast path: all 4 loads issued back-to-back (MLP=4), then compute,
        // then 4 independent stores.
        float4 xv[ELTS];
#pragma unroll
        for (int e = 0; e < ELTS; e++)
            xv[e] = reinterpret_cast<const float4*>(x)[(b0 + e) * 2];

        float4 o[ELTS];
#pragma unroll
        for (int e = 0; e < ELTS; e++) {
            float s0, c0, s1, c1, s2, c2, s3, c3;
            __sincosf(xv[e].x, &s0, &c0);
            __sincosf(xv[e].y, &s1, &c1);
            __sincosf(xv[e].z, &s2, &c2);
            __sincosf(xv[e].w, &s3, &c3);

            float d0 = c0;
            float d1 = d0 * c1;
            float d2 = d1 * c2;
            float d3 = d2 * c3;

            o[e].x = fmaf(cw0, d0, -sw0 * (s0 * s1));
            o[e].y = fmaf(cw1, d1, -sw1 * (s1 * s2));
            o[e].z = fmaf(cw2, d2, -sw2 * (s2 * s3));
            o[e].w = fmaf(cw3, d3, -sw3 * s3);
        }

#pragma unroll
        for (int e = 0; e < ELTS; e++)
            reinterpret_cast<float4*>(out)[b0 + e] = o[e];
    } else {
        // Tail (empty when n % (256*ELTS) == 0, e.g. B = 1M).
        for (int b = b0; b < n; b++) {
            float4 xv = reinterpret_cast<const float4*>(x)[b * 2];
            float s0, c0, s1, c1, s2, c2, s3, c3;
            __sincosf(xv.x, &s0, &c0);
            __sincosf(xv.y, &s1, &c1);
            __sincosf(xv.z, &s2, &c2);
            __sincosf(xv.w, &s3, &c3);

            float d0 = c0;
            float d1 = d0 * c1;
            float d2 = d1 * c2;
            float d3 = d2 * c3;

            float4 o;
            o.x = fmaf(cw0, d0, -sw0 * (s0 * s1));
            o.y = fmaf(cw1, d1, -sw1 * (s1 * s2));
            o.z = fmaf(cw2, d2, -sw2 * (s2 * s3));
            o.w = fmaf(cw3, d3, -sw3 * s3);
            reinterpret_cast<float4*>(out)[b] = o;
        }
    }
}

extern "C" void kernel_launch(void* const* d_in, const int* in_sizes, int n_in,
                              void* d_out, int out_size) {
    const float* x = (const float*)d_in[0];        // [B, 8]
    const float* weights = (const float*)d_in[1];  // [4]
    float* out = (float*)d_out;                    // [B, 4]
    int n = in_sizes[0] / 8;

    int threads = 256;
    int elts_per_block = threads * ELTS;
    int blocks = (n + elts_per_block - 1) / elts_per_block;
    qlayer_kernel<<<blocks, threads>>>(x, weights, out, n);
}